// round 2
// baseline (speedup 1.0000x reference)
#include <cuda_runtime.h>
#include <cuda_bf16.h>
#include <math.h>

// Problem constants (fixed by reference setup_inputs):
//   n = 100000 nodes, seq_len = 4, hidden = 128, n_edges = 1.6M
#define MAX_N     100000
#define HIDDEN    128
#define SEQ_STRIDE (4 * 128)   // floats per node in semantics

// Scratch: accumulators for sum of semantics[src,0,:] per target node, counts,
// and a flag telling the scatter kernel how edge_index is encoded.
__device__ float g_sums[MAX_N * HIDDEN];   // 51.2 MB
__device__ float g_cnt[MAX_N];
__device__ int   g_idx_is_64;              // 1 = int64 indices, 0 = int32

// ---------------------------------------------------------------------------
// Probe: decide whether edge_index is genuine int64 or packed int32 pairs.
// If the buffer really holds int32 pairs, reading it as int64 produces values
// with a (almost surely) nonzero upper word -> out of [0, n) -> int32 mode.
// ---------------------------------------------------------------------------
__global__ void probe_dtype_kernel(const long long* __restrict__ ei64,
                                   int n_pairs_to_check, long long n) {
    if (threadIdx.x != 0 || blockIdx.x != 0) return;
    int is64 = 1;
    for (int i = 0; i < n_pairs_to_check; i++) {
        long long v = ei64[i];
        if (v < 0 || v >= n) { is64 = 0; break; }
    }
    g_idx_is_64 = is64;
}

// ---------------------------------------------------------------------------
// Phase B: one warp per edge. Gather 128 floats of semantics[src,0,:] and
// vector-reduce (red.global.add.v4.f32) into g_sums[tgt]. Lane 0 bumps count.
// ---------------------------------------------------------------------------
__global__ void scatter_kernel(const float* __restrict__ sem,
                               const void* __restrict__ ei_raw,
                               int n_edges) {
    int warp = (blockIdx.x * blockDim.x + threadIdx.x) >> 5;
    int lane = threadIdx.x & 31;
    if (warp >= n_edges) return;

    long long src, tgt;
    if (g_idx_is_64) {
        const long long* ei = (const long long*)ei_raw;
        src = __ldg(ei + 2LL * warp);
        tgt = __ldg(ei + 2LL * warp + 1);
    } else {
        const int* ei = (const int*)ei_raw;
        src = __ldg(ei + 2LL * warp);
        tgt = __ldg(ei + 2LL * warp + 1);
    }

    const float4 v = *reinterpret_cast<const float4*>(
        sem + src * SEQ_STRIDE + lane * 4);

    float* dst = g_sums + tgt * HIDDEN + lane * 4;
    asm volatile("red.global.add.v4.f32 [%0], {%1, %2, %3, %4};"
                 :: "l"(dst), "f"(v.x), "f"(v.y), "f"(v.z), "f"(v.w)
                 : "memory");

    if (lane == 0) atomicAdd(&g_cnt[tgt], 1.0f);
}

// ---------------------------------------------------------------------------
// Phase C: fused (sums @ W) / max(cnt,1) -> exact GELU -> out.
// One block of 128 threads handles RPB rows; thread j owns output column j.
// W row k is loaded once per block-iteration and reused across RPB rows.
// ---------------------------------------------------------------------------
#define RPB 8
__global__ void gemm_mean_gelu_kernel(const float* __restrict__ W,
                                      float* __restrict__ out,
                                      int n) {
    __shared__ float s[RPB][HIDDEN];
    const int r0 = blockIdx.x * RPB;
    const int j  = threadIdx.x;   // 0..127

    #pragma unroll
    for (int r = 0; r < RPB; r++) {
        int row = r0 + r;
        s[r][j] = (row < n) ? g_sums[(size_t)row * HIDDEN + j] : 0.0f;
    }
    __syncthreads();

    float acc[RPB];
    #pragma unroll
    for (int r = 0; r < RPB; r++) acc[r] = 0.0f;

    #pragma unroll 4
    for (int k = 0; k < HIDDEN; k++) {
        float w = __ldg(W + k * HIDDEN + j);
        #pragma unroll
        for (int r = 0; r < RPB; r++) acc[r] = fmaf(s[r][k], w, acc[r]);
    }

    #pragma unroll
    for (int r = 0; r < RPB; r++) {
        int row = r0 + r;
        if (row < n) {
            float c = g_cnt[row];
            float m = acc[r] / fmaxf(c, 1.0f);
            // exact GELU: 0.5*x*(1 + erf(x/sqrt(2)))
            out[(size_t)row * HIDDEN + j] =
                0.5f * m * (1.0f + erff(m * 0.70710678118654752f));
        }
    }
}

// ---------------------------------------------------------------------------
// kernel_launch: probe dtype -> memset scratch -> scatter -> fused gemm.
// All async on the default stream; graph-capturable; no allocations.
// Input order (metadata): semantics, attention_masks (unused), W, edge_index.
// ---------------------------------------------------------------------------
extern "C" void kernel_launch(void* const* d_in, const int* in_sizes, int n_in,
                              void* d_out, int out_size) {
    const float* sem = (const float*)d_in[0];
    const float* W   = (const float*)d_in[2];
    const void*  ei  = d_in[3];
    float* out = (float*)d_out;

    const int n       = in_sizes[0] / SEQ_STRIDE;   // 100000
    const int n_edges = in_sizes[3] / 2;            // 1600000

    void* sums_ptr = nullptr;
    void* cnt_ptr  = nullptr;
    cudaGetSymbolAddress(&sums_ptr, g_sums);
    cudaGetSymbolAddress(&cnt_ptr,  g_cnt);

    // Probe interprets the first 512 int64-sized slots (safe: buffer holds
    // >= 3.2M int32 = 1.6M int64 slots either way).
    probe_dtype_kernel<<<1, 32>>>((const long long*)ei, 512, (long long)n);

    cudaMemsetAsync(sums_ptr, 0, (size_t)n * HIDDEN * sizeof(float));
    cudaMemsetAsync(cnt_ptr,  0, (size_t)n * sizeof(float));

    // one warp per edge, 8 edges per 256-thread block
    int blocks_scatter = (n_edges + 7) / 8;
    scatter_kernel<<<blocks_scatter, 256>>>(sem, ei, n_edges);

    int blocks_gemm = (n + RPB - 1) / RPB;
    gemm_mean_gelu_kernel<<<blocks_gemm, HIDDEN>>>(W, out, n);
}